// round 1
// baseline (speedup 1.0000x reference)
#include <cuda_runtime.h>

#define NN 4096
#define MM 4096
#define DD 8

// Scratch in __device__ globals (no allocation allowed).
// SoA layout so the main kernel's shared-tile loads are coalesced.
__device__ float g_as[DD][NN];   // a[d][i] = x[i][d]/scale[d] * sqrt(log2 e)
__device__ float g_bs[DD][MM];   // b[d][j] = xx[j][d]/scale[d] * sqrt(log2 e)
__device__ float g_an[NN];       // -0.5*||a_i||^2 + log2(variance)
__device__ float g_bn[MM];       // -0.5*||b_j||^2

// out[i][j] = exp2( g_an[i] + g_bn[j] + sum_d a[d][i]*b[d][j] )
//           = variance * exp(-0.5 * sum_d ((x-xx)/scale)^2)

__global__ void rbf_prep(const float* __restrict__ x,
                         const float* __restrict__ xx,
                         const float* __restrict__ log_scale,
                         const float* __restrict__ log_variance) {
    __shared__ float inv_s[DD];
    if (threadIdx.x < DD) {
        // 1/scale * sqrt(log2(e)); sqrt so the dot product carries log2(e) once.
        inv_s[threadIdx.x] = expf(-log_scale[threadIdx.x]) * 1.2011224087864498f;
    }
    __syncthreads();
    const int i = blockIdx.x * blockDim.x + threadIdx.x;
    const float l2var = log_variance[0] * 1.4426950408889634f;  // log2(variance)

    if (i < NN) {
        float s = 0.f;
        #pragma unroll
        for (int d = 0; d < DD; d++) {
            float v = x[i * DD + d] * inv_s[d];
            g_as[d][i] = v;
            s = fmaf(v, v, s);
        }
        g_an[i] = fmaf(-0.5f, s, l2var);
    }
    if (i < MM) {
        float s = 0.f;
        #pragma unroll
        for (int d = 0; d < DD; d++) {
            float v = xx[i * DD + d] * inv_s[d];
            g_bs[d][i] = v;
            s = fmaf(v, v, s);
        }
        g_bn[i] = -0.5f * s;
    }
}

__global__ __launch_bounds__(256) void rbf_main(float* __restrict__ out) {
    __shared__ float sA[DD][64];
    __shared__ float sB[DD][64];
    __shared__ float sAn[64];
    __shared__ float sBn[64];

    const int bi = blockIdx.y * 64;
    const int bj = blockIdx.x * 64;
    const int tid = threadIdx.x;

    // Load 64-row tiles of both operands (SoA): 512 floats each side.
    #pragma unroll
    for (int k = tid; k < 512; k += 256) {
        const int d = k >> 6, c = k & 63;
        sA[d][c] = g_as[d][bi + c];
        sB[d][c] = g_bs[d][bj + c];
    }
    if (tid < 64) sAn[tid] = g_an[bi + tid];
    else if (tid < 128) sBn[tid - 64] = g_bn[bj + tid - 64];
    __syncthreads();

    // 4x4 register tile per thread, strided by 16 in both dims:
    //  - sA reads broadcast within each half-warp (same ti)
    //  - sB reads are 16 consecutive floats (conflict-free)
    //  - stores: each half-warp writes 64 contiguous bytes per (u,v)
    const int ti = tid >> 4;   // 0..15
    const int tj = tid & 15;   // 0..15

    float a[4][DD], an[4];
    #pragma unroll
    for (int u = 0; u < 4; u++) {
        const int i = ti + 16 * u;
        #pragma unroll
        for (int d = 0; d < DD; d++) a[u][d] = sA[d][i];
        an[u] = sAn[i];
    }

    #pragma unroll
    for (int v = 0; v < 4; v++) {
        const int j = tj + 16 * v;
        float b[DD];
        #pragma unroll
        for (int d = 0; d < DD; d++) b[d] = sB[d][j];
        const float bn = sBn[j];

        #pragma unroll
        for (int u = 0; u < 4; u++) {
            float e = an[u] + bn;
            #pragma unroll
            for (int d = 0; d < DD; d++) e = fmaf(a[u][d], b[d], e);
            out[(size_t)(bi + ti + 16 * u) * MM + (bj + j)] = exp2f(e);
        }
    }
}

extern "C" void kernel_launch(void* const* d_in, const int* in_sizes, int n_in,
                              void* d_out, int out_size) {
    const float* x      = (const float*)d_in[0];
    const float* xx     = (const float*)d_in[1];
    const float* lscale = (const float*)d_in[2];
    const float* lvar   = (const float*)d_in[3];
    float* out          = (float*)d_out;

    rbf_prep<<<(NN + 255) / 256, 256>>>(x, xx, lscale, lvar);
    dim3 grid(MM / 64, NN / 64);
    rbf_main<<<grid, 256>>>(out);
}

// round 2
// speedup vs baseline: 1.2553x; 1.2553x over previous
#include <cuda_runtime.h>

#define NN 4096
#define MM 4096
#define DD 8

typedef unsigned long long u64;

// ---- device scratch (no allocations allowed) ----
__device__ float g_as[NN * DD];   // AoS: g_as[i*8+d] = x[i][d]/scale[d]*sqrt(log2 e)
__device__ float g_bs[DD * MM];   // SoA: g_bs[d*M+j] = xx[j][d]/scale[d]*sqrt(log2 e)
__device__ float g_an[NN];        // -0.5*||a_i||^2 + log2(variance)
__device__ float g_bn[MM];        // -0.5*||b_j||^2

// out[i][j] = exp2( an[i] + bn[j] + sum_d a[i][d]*b[j][d] )

// ---- packed f32x2 helpers (sm_103a) ----
__device__ __forceinline__ u64 fma2(u64 a, u64 b, u64 c) {
    u64 d; asm("fma.rn.f32x2 %0, %1, %2, %3;" : "=l"(d) : "l"(a), "l"(b), "l"(c)); return d;
}
__device__ __forceinline__ u64 add2(u64 a, u64 b) {
    u64 d; asm("add.rn.f32x2 %0, %1, %2;" : "=l"(d) : "l"(a), "l"(b)); return d;
}
__device__ __forceinline__ u64 pack2(float x, float y) {
    u64 r; asm("mov.b64 %0, {%1,%2};" : "=l"(r) : "f"(x), "f"(y)); return r;
}
__device__ __forceinline__ float lo2(u64 v) { return __uint_as_float((unsigned)v); }
__device__ __forceinline__ float hi2(u64 v) { return __uint_as_float((unsigned)(v >> 32)); }
__device__ __forceinline__ float ex2(float x) {
    float r; asm("ex2.approx.f32 %0, %1;" : "=f"(r) : "f"(x)); return r;
}

__global__ void rbf_prep(const float* __restrict__ x,
                         const float* __restrict__ xx,
                         const float* __restrict__ log_scale,
                         const float* __restrict__ log_variance) {
    __shared__ float inv_s[DD];
    if (threadIdx.x < DD) {
        // 1/scale * sqrt(log2 e): carries log2(e) once through the dot product
        inv_s[threadIdx.x] = expf(-log_scale[threadIdx.x]) * 1.2011224087864498f;
    }
    __syncthreads();
    const int i = blockIdx.x * blockDim.x + threadIdx.x;
    const float l2var = log_variance[0] * 1.4426950408889634f;

    if (i < NN) {
        float s = 0.f;
        #pragma unroll
        for (int d = 0; d < DD; d++) {
            float v = x[i * DD + d] * inv_s[d];
            g_as[i * DD + d] = v;            // AoS
            s = fmaf(v, v, s);
        }
        g_an[i] = fmaf(-0.5f, s, l2var);
    }
    if (i < MM) {
        float s = 0.f;
        #pragma unroll
        for (int d = 0; d < DD; d++) {
            float v = xx[i * DD + d] * inv_s[d];
            g_bs[d * MM + i] = v;            // SoA
            s = fmaf(v, v, s);
        }
        g_bn[i] = -0.5f * s;
    }
}

// CTA tile: 64 (i) x 128 (j). 256 threads, 32 outputs/thread:
//   ti = tid>>4 (0..15), i = ti + 16*u, u=0..3
//   tj = tid&15, two j-quads: jA = 4*tj, jB = 64 + 4*tj
__global__ __launch_bounds__(256) void rbf_main(float* __restrict__ out) {
    __shared__ u64    sA2[64][DD];     // pre-splatted {a,a}   (4KB)
    __shared__ float4 sB4[DD][32];     // b quads, d-major     (4KB)
    __shared__ u64    sAn2[64];        // pre-splatted {an,an} (512B)
    __shared__ float  sBn[128];        // (512B)

    const int bi = blockIdx.y * 64;
    const int bj = blockIdx.x * 128;
    const int tid = threadIdx.x;

    // --- fill ---
    #pragma unroll
    for (int k = tid; k < 512; k += 256) {        // A: 64 rows x 8 dims, splat
        const int c = k >> 3, d = k & 7;
        const float v = g_as[(bi + c) * DD + d];
        sA2[c][d] = pack2(v, v);
    }
    {                                             // B: 8 dims x 32 quads
        const int d = tid >> 5, q = tid & 31;
        sB4[d][q] = ((const float4*)(g_bs + d * MM + bj))[q];
    }
    if (tid < 64) {
        const float v = g_an[bi + tid];
        sAn2[tid] = pack2(v, v);
    } else if (tid < 192) {
        sBn[tid - 64] = g_bn[bj + tid - 64];
    }
    __syncthreads();

    const int ti = tid >> 4;
    const int tj = tid & 15;

    // init accumulators: e[u][p] = {an,an} + bn_pair
    u64 e[4][4];
    {
        const ulonglong2 bnA = *(const ulonglong2*)&sBn[4 * tj];
        const ulonglong2 bnB = *(const ulonglong2*)&sBn[64 + 4 * tj];
        #pragma unroll
        for (int u = 0; u < 4; u++) {
            const u64 anu = sAn2[ti + 16 * u];
            e[u][0] = add2(anu, bnA.x);
            e[u][1] = add2(anu, bnA.y);
            e[u][2] = add2(anu, bnB.x);
            e[u][3] = add2(anu, bnB.y);
        }
    }

    // main: 8 dims x 4 rows x 4 pairs of FFMA2
    #pragma unroll
    for (int d = 0; d < DD; d++) {
        const ulonglong2 bA = *(const ulonglong2*)&sB4[d][tj];
        const ulonglong2 bB = *(const ulonglong2*)&sB4[d][16 + tj];
        #pragma unroll
        for (int u = 0; u < 4; u++) {
            const u64 aa = sA2[ti + 16 * u][d];
            e[u][0] = fma2(aa, bA.x, e[u][0]);
            e[u][1] = fma2(aa, bA.y, e[u][1]);
            e[u][2] = fma2(aa, bB.x, e[u][2]);
            e[u][3] = fma2(aa, bB.y, e[u][3]);
        }
    }

    // epilogue: exp2 + vector stores
    #pragma unroll
    for (int u = 0; u < 4; u++) {
        const size_t row = (size_t)(bi + ti + 16 * u) * MM;
        float4 rA, rB;
        rA.x = ex2(lo2(e[u][0])); rA.y = ex2(hi2(e[u][0]));
        rA.z = ex2(lo2(e[u][1])); rA.w = ex2(hi2(e[u][1]));
        rB.x = ex2(lo2(e[u][2])); rB.y = ex2(hi2(e[u][2]));
        rB.z = ex2(lo2(e[u][3])); rB.w = ex2(hi2(e[u][3]));
        *(float4*)(out + row + bj + 4 * tj)      = rA;
        *(float4*)(out + row + bj + 64 + 4 * tj) = rB;
    }
}

extern "C" void kernel_launch(void* const* d_in, const int* in_sizes, int n_in,
                              void* d_out, int out_size) {
    const float* x      = (const float*)d_in[0];
    const float* xx     = (const float*)d_in[1];
    const float* lscale = (const float*)d_in[2];
    const float* lvar   = (const float*)d_in[3];
    float* out          = (float*)d_out;

    rbf_prep<<<(NN + 255) / 256, 256>>>(x, xx, lscale, lvar);
    dim3 grid(MM / 128, NN / 64);
    rbf_main<<<grid, 256>>>(out);
}

// round 3
// speedup vs baseline: 1.3873x; 1.1052x over previous
#include <cuda_runtime.h>

#define NN 4096
#define MM 4096
#define DD 8

typedef unsigned long long u64;

// out[i][j] = exp2( an[i] + bn[j] + sum_d a[i][d]*b[j][d] )
//   a = x/scale * sqrt(log2 e),  an = -0.5||a||^2 + log2(var),  bn = -0.5||b||^2

__device__ __forceinline__ u64 fma2(u64 a, u64 b, u64 c) {
    u64 d; asm("fma.rn.f32x2 %0, %1, %2, %3;" : "=l"(d) : "l"(a), "l"(b), "l"(c)); return d;
}
__device__ __forceinline__ u64 add2(u64 a, u64 b) {
    u64 d; asm("add.rn.f32x2 %0, %1, %2;" : "=l"(d) : "l"(a), "l"(b)); return d;
}
__device__ __forceinline__ u64 pack2(float x, float y) {
    u64 r; asm("mov.b64 %0, {%1,%2};" : "=l"(r) : "f"(x), "f"(y)); return r;
}
__device__ __forceinline__ float lo2(u64 v) { return __uint_as_float((unsigned)v); }
__device__ __forceinline__ float hi2(u64 v) { return __uint_as_float((unsigned)(v >> 32)); }
__device__ __forceinline__ float ex2(float x) {
    float r; asm("ex2.approx.f32 %0, %1;" : "=f"(r) : "f"(x)); return r;
}

// One fused kernel. CTA tile: 64 (i) x 128 (j), 256 threads, 32 outputs/thread.
__global__ __launch_bounds__(256, 4) void rbf_main(
    const float* __restrict__ x,
    const float* __restrict__ xx,
    const float* __restrict__ log_scale,
    const float* __restrict__ log_variance,
    float* __restrict__ out)
{
    __shared__ float  s_inv[DD];       // 1/scale * sqrt(log2 e)
    __shared__ u64    sA2[64][DD];     // pre-splatted {a,a}       (4KB)
    __shared__ float  sB [DD][128];    // b, d-major               (4KB)
    __shared__ u64    sAn2[64];        // pre-splatted {an,an}
    __shared__ float  sBn[128];

    const int bi = blockIdx.y * 64;
    const int bj = blockIdx.x * 128;
    const int tid = threadIdx.x;

    if (tid < DD) {
        // exp(-log_scale) * sqrt(log2 e) via exact-enough ex2
        s_inv[tid] = ex2(-log_scale[tid] * 1.4426950408889634f) * 1.2011224087864498f;
    }
    __syncthreads();

    // ---- fused prep ----
    if (tid < 64) {
        // A row i = bi + tid
        const float4 p0 = ((const float4*)(x + (size_t)(bi + tid) * DD))[0];
        const float4 p1 = ((const float4*)(x + (size_t)(bi + tid) * DD))[1];
        float a[DD];
        a[0] = p0.x * s_inv[0]; a[1] = p0.y * s_inv[1];
        a[2] = p0.z * s_inv[2]; a[3] = p0.w * s_inv[3];
        a[4] = p1.x * s_inv[4]; a[5] = p1.y * s_inv[5];
        a[6] = p1.z * s_inv[6]; a[7] = p1.w * s_inv[7];
        float s = 0.f;
        #pragma unroll
        for (int d = 0; d < DD; d++) { sA2[tid][d] = pack2(a[d], a[d]); s = fmaf(a[d], a[d], s); }
        sAn2[tid] = pack2(fmaf(-0.5f, s, log_variance[0] * 1.4426950408889634f),
                          fmaf(-0.5f, s, log_variance[0] * 1.4426950408889634f));
    } else if (tid < 192) {
        // B col j = bj + (tid - 64)
        const int j = tid - 64;
        const float4 p0 = ((const float4*)(xx + (size_t)(bj + j) * DD))[0];
        const float4 p1 = ((const float4*)(xx + (size_t)(bj + j) * DD))[1];
        float b[DD];
        b[0] = p0.x * s_inv[0]; b[1] = p0.y * s_inv[1];
        b[2] = p0.z * s_inv[2]; b[3] = p0.w * s_inv[3];
        b[4] = p1.x * s_inv[4]; b[5] = p1.y * s_inv[5];
        b[6] = p1.z * s_inv[6]; b[7] = p1.w * s_inv[7];
        float s = 0.f;
        #pragma unroll
        for (int d = 0; d < DD; d++) { sB[d][j] = b[d]; s = fmaf(b[d], b[d], s); }
        sBn[j] = -0.5f * s;
    }
    __syncthreads();

    // ---- main compute ----
    const int ti = tid >> 4;   // 0..15, i = ti + 16u
    const int tj = tid & 15;   // 0..15, j quads at 4*tj and 64+4*tj

    u64 e[4][4];
    {
        const ulonglong2 bnA = *(const ulonglong2*)&sBn[4 * tj];
        const ulonglong2 bnB = *(const ulonglong2*)&sBn[64 + 4 * tj];
        #pragma unroll
        for (int u = 0; u < 4; u++) {
            const u64 anu = sAn2[ti + 16 * u];
            e[u][0] = add2(anu, bnA.x);
            e[u][1] = add2(anu, bnA.y);
            e[u][2] = add2(anu, bnB.x);
            e[u][3] = add2(anu, bnB.y);
        }
    }

    #pragma unroll
    for (int d = 0; d < DD; d++) {
        const ulonglong2 bA = *(const ulonglong2*)&sB[d][4 * tj];
        const ulonglong2 bB = *(const ulonglong2*)&sB[d][64 + 4 * tj];
        #pragma unroll
        for (int u = 0; u < 4; u++) {
            const u64 aa = sA2[ti + 16 * u][d];
            e[u][0] = fma2(aa, bA.x, e[u][0]);
            e[u][1] = fma2(aa, bA.y, e[u][1]);
            e[u][2] = fma2(aa, bB.x, e[u][2]);
            e[u][3] = fma2(aa, bB.y, e[u][3]);
        }
    }

    #pragma unroll
    for (int u = 0; u < 4; u++) {
        const size_t row = (size_t)(bi + ti + 16 * u) * MM;
        float4 rA, rB;
        rA.x = ex2(lo2(e[u][0])); rA.y = ex2(hi2(e[u][0]));
        rA.z = ex2(lo2(e[u][1])); rA.w = ex2(hi2(e[u][1]));
        rB.x = ex2(lo2(e[u][2])); rB.y = ex2(hi2(e[u][2]));
        rB.z = ex2(lo2(e[u][3])); rB.w = ex2(hi2(e[u][3]));
        *(float4*)(out + row + bj + 4 * tj)      = rA;
        *(float4*)(out + row + bj + 64 + 4 * tj) = rB;
    }
}

extern "C" void kernel_launch(void* const* d_in, const int* in_sizes, int n_in,
                              void* d_out, int out_size) {
    const float* x      = (const float*)d_in[0];
    const float* xx     = (const float*)d_in[1];
    const float* lscale = (const float*)d_in[2];
    const float* lvar   = (const float*)d_in[3];
    float* out          = (float*)d_out;

    dim3 grid(MM / 128, NN / 64);
    rbf_main<<<grid, 256>>>(x, xx, lscale, lvar, out);
}